// round 1
// baseline (speedup 1.0000x reference)
#include <cuda_runtime.h>

// SelfAttentionLayer: per (b,h) row of the image, W=64 "tokens" of C=256 channels.
//   Q = X Wq + bq ; K = X Wk + bk ; V = X Wv + bv        (X = x[b,h] : [64,256])
//   S[w][v] = sum_c K[w][c] * Q[v][c]   (NO 1/sqrt(d) scale)
//   P = softmax over v (last axis)
//   O[w][c] = sum_v P[w][v] * V[v][c]
//   out = O * X (elementwise gate)
//
// Fully fused: one CTA per (b,h), all intermediates in shared memory.

#define Wn 64
#define Cn 256
#define XS 260   // padded row stride (floats) for 64x256 smem tiles: .128 loads hit disjoint bank quads
#define SS 68    // padded row stride for the 64x64 score tile

#define SMEM_FLOATS (3 * Wn * XS + Wn * SS)
#define SMEM_BYTES  (SMEM_FLOATS * 4)

// acc[0..7] += xv * {A.xyzw, B.xyzw}
#define FMA8(ACC, XV, A, B)                         \
    do {                                            \
        ACC[0] = fmaf((XV), (A).x, ACC[0]);         \
        ACC[1] = fmaf((XV), (A).y, ACC[1]);         \
        ACC[2] = fmaf((XV), (A).z, ACC[2]);         \
        ACC[3] = fmaf((XV), (A).w, ACC[3]);         \
        ACC[4] = fmaf((XV), (B).x, ACC[4]);         \
        ACC[5] = fmaf((XV), (B).y, ACC[5]);         \
        ACC[6] = fmaf((XV), (B).z, ACC[6]);         \
        ACC[7] = fmaf((XV), (B).w, ACC[7]);         \
    } while (0)

// dst[64,256](+pad) = sX[64,256](+pad) @ W[256,256] + bias, 8x8 tile per thread.
__device__ __forceinline__ void proj_gemm(
    const float* __restrict__ sX, float* __restrict__ dst,
    const float* __restrict__ W, const float* __restrict__ bias,
    int r0, int c0)
{
    float acc[8][8];
#pragma unroll
    for (int i = 0; i < 8; i++)
#pragma unroll
        for (int j = 0; j < 8; j++) acc[i][j] = 0.f;

#pragma unroll 2
    for (int k = 0; k < Cn; k += 4) {
        float4 xf[8];
#pragma unroll
        for (int r = 0; r < 8; r++)
            xf[r] = *reinterpret_cast<const float4*>(&sX[(r0 + r) * XS + k]);  // broadcast within warp

        float4 wa[4], wb[4];
#pragma unroll
        for (int kk = 0; kk < 4; kk++) {
            wa[kk] = *reinterpret_cast<const float4*>(&W[(size_t)(k + kk) * Cn + c0]);
            wb[kk] = *reinterpret_cast<const float4*>(&W[(size_t)(k + kk) * Cn + c0 + 4]);
        }

#pragma unroll
        for (int kk = 0; kk < 4; kk++) {
#pragma unroll
            for (int r = 0; r < 8; r++) {
                float xv = (kk == 0) ? xf[r].x : (kk == 1) ? xf[r].y
                         : (kk == 2) ? xf[r].z : xf[r].w;
                FMA8(acc[r], xv, wa[kk], wb[kk]);
            }
        }
    }

    float4 b0 = *reinterpret_cast<const float4*>(&bias[c0]);
    float4 b1 = *reinterpret_cast<const float4*>(&bias[c0 + 4]);
#pragma unroll
    for (int r = 0; r < 8; r++) {
        float4 o0 = make_float4(acc[r][0] + b0.x, acc[r][1] + b0.y,
                                acc[r][2] + b0.z, acc[r][3] + b0.w);
        float4 o1 = make_float4(acc[r][4] + b1.x, acc[r][5] + b1.y,
                                acc[r][6] + b1.z, acc[r][7] + b1.w);
        *reinterpret_cast<float4*>(&dst[(r0 + r) * XS + c0])     = o0;
        *reinterpret_cast<float4*>(&dst[(r0 + r) * XS + c0 + 4]) = o1;
    }
}

__global__ void __launch_bounds__(256, 1)
attn_fused_kernel(const float* __restrict__ x,
                  const float* __restrict__ wq, const float* __restrict__ bq,
                  const float* __restrict__ wk, const float* __restrict__ bk,
                  const float* __restrict__ wv, const float* __restrict__ bv,
                  float* __restrict__ out)
{
    extern __shared__ float smem[];
    float* sX  = smem;                 // [64][260] raw input tile (kept for the gate)
    float* sQ  = sX  + Wn * XS;        // [64][260] Q
    float* sKV = sQ  + Wn * XS;        // [64][260] K, later overwritten with V
    float* sS  = sKV + Wn * XS;        // [64][68]  scores -> probabilities

    const int tid = threadIdx.x;
    const size_t bh = blockIdx.x;
    const float* xg = x   + bh * (size_t)(Wn * Cn);
    float*       og = out + bh * (size_t)(Wn * Cn);

    // ---- P0: stage X ----
    for (int i = tid; i < Wn * Cn / 4; i += 256) {
        int r = i >> 6;            // 64 float4 per row
        int c = (i & 63) << 2;
        float4 v = reinterpret_cast<const float4*>(xg)[i];
        *reinterpret_cast<float4*>(&sX[r * XS + c]) = v;
    }
    __syncthreads();

    const int rtile = tid >> 5;    // warp id, 0..7
    const int ctile = tid & 31;    // lane
    const int r0 = rtile << 3;
    const int c0 = ctile << 3;

    // ---- P1: Q and K projections ----
    proj_gemm(sX, sQ,  wq, bq, r0, c0);
    proj_gemm(sX, sKV, wk, bk, r0, c0);
    __syncthreads();

    // ---- P2: S = K Q^T  (warp owns 8 q-rows, lane owns k-rows {lane, lane+32}) ----
    {
        const int v0 = r0;         // this warp's q-row block
        const int w0 = ctile;
        float a0[8], a1[8];
#pragma unroll
        for (int j = 0; j < 8; j++) { a0[j] = 0.f; a1[j] = 0.f; }

#pragma unroll 2
        for (int c = 0; c < Cn; c += 4) {
            float4 k0 = *reinterpret_cast<const float4*>(&sKV[w0 * XS + c]);
            float4 k1 = *reinterpret_cast<const float4*>(&sKV[(w0 + 32) * XS + c]);
#pragma unroll
            for (int j = 0; j < 8; j++) {
                float4 q = *reinterpret_cast<const float4*>(&sQ[(v0 + j) * XS + c]); // broadcast
                a0[j] = fmaf(k0.x, q.x, fmaf(k0.y, q.y, fmaf(k0.z, q.z, fmaf(k0.w, q.w, a0[j]))));
                a1[j] = fmaf(k1.x, q.x, fmaf(k1.y, q.y, fmaf(k1.z, q.z, fmaf(k1.w, q.w, a1[j]))));
            }
        }
        *reinterpret_cast<float4*>(&sS[w0 * SS + v0])            = make_float4(a0[0], a0[1], a0[2], a0[3]);
        *reinterpret_cast<float4*>(&sS[w0 * SS + v0 + 4])        = make_float4(a0[4], a0[5], a0[6], a0[7]);
        *reinterpret_cast<float4*>(&sS[(w0 + 32) * SS + v0])     = make_float4(a1[0], a1[1], a1[2], a1[3]);
        *reinterpret_cast<float4*>(&sS[(w0 + 32) * SS + v0 + 4]) = make_float4(a1[4], a1[5], a1[6], a1[7]);
    }
    __syncthreads();

    // ---- P3: row softmax over v (warp handles rows r0..r0+7) ----
    {
        const int lane = ctile;
#pragma unroll
        for (int rr = 0; rr < 8; rr++) {
            int r = r0 + rr;
            float aa = sS[r * SS + lane];
            float bb = sS[r * SS + lane + 32];
            float m = fmaxf(aa, bb);
#pragma unroll
            for (int off = 16; off > 0; off >>= 1)
                m = fmaxf(m, __shfl_xor_sync(0xffffffffu, m, off));
            float e0 = __expf(aa - m);
            float e1 = __expf(bb - m);
            float s = e0 + e1;
#pragma unroll
            for (int off = 16; off > 0; off >>= 1)
                s += __shfl_xor_sync(0xffffffffu, s, off);
            float inv = 1.0f / s;
            sS[r * SS + lane]      = e0 * inv;
            sS[r * SS + lane + 32] = e1 * inv;
        }
    }

    // ---- P4: V projection (overwrite K buffer; P2 reads of sKV completed before last sync) ----
    proj_gemm(sX, sKV, wv, bv, r0, c0);
    __syncthreads();

    // ---- P5: O = P V, gate with X, store ----
    {
        float acc[8][8];
#pragma unroll
        for (int i = 0; i < 8; i++)
#pragma unroll
            for (int j = 0; j < 8; j++) acc[i][j] = 0.f;

#pragma unroll 2
        for (int v = 0; v < Wn; v += 4) {
            float4 pf[8];
#pragma unroll
            for (int r = 0; r < 8; r++)
                pf[r] = *reinterpret_cast<const float4*>(&sS[(r0 + r) * SS + v]); // broadcast

            float4 va[4], vb[4];
#pragma unroll
            for (int vv = 0; vv < 4; vv++) {
                va[vv] = *reinterpret_cast<const float4*>(&sKV[(v + vv) * XS + c0]);
                vb[vv] = *reinterpret_cast<const float4*>(&sKV[(v + vv) * XS + c0 + 4]);
            }
#pragma unroll
            for (int vv = 0; vv < 4; vv++) {
#pragma unroll
                for (int r = 0; r < 8; r++) {
                    float p = (vv == 0) ? pf[r].x : (vv == 1) ? pf[r].y
                            : (vv == 2) ? pf[r].z : pf[r].w;
                    FMA8(acc[r], p, va[vv], vb[vv]);
                }
            }
        }

#pragma unroll
        for (int r = 0; r < 8; r++) {
            float4 x0 = *reinterpret_cast<const float4*>(&sX[(r0 + r) * XS + c0]);
            float4 x1 = *reinterpret_cast<const float4*>(&sX[(r0 + r) * XS + c0 + 4]);
            float4 o0 = make_float4(acc[r][0] * x0.x, acc[r][1] * x0.y,
                                    acc[r][2] * x0.z, acc[r][3] * x0.w);
            float4 o1 = make_float4(acc[r][4] * x1.x, acc[r][5] * x1.y,
                                    acc[r][6] * x1.z, acc[r][7] * x1.w);
            *reinterpret_cast<float4*>(&og[(r0 + r) * Cn + c0])     = o0;
            *reinterpret_cast<float4*>(&og[(r0 + r) * Cn + c0 + 4]) = o1;
        }
    }
}

extern "C" void kernel_launch(void* const* d_in, const int* in_sizes, int n_in,
                              void* d_out, int out_size)
{
    const float* x  = (const float*)d_in[0];
    const float* wq = (const float*)d_in[1];
    const float* bq = (const float*)d_in[2];
    const float* wk = (const float*)d_in[3];
    const float* bk = (const float*)d_in[4];
    const float* wv = (const float*)d_in[5];
    const float* bv = (const float*)d_in[6];
    float* out = (float*)d_out;

    int n_bh = in_sizes[0] / (Wn * Cn);   // B*H = 2048

    cudaFuncSetAttribute(attn_fused_kernel,
                         cudaFuncAttributeMaxDynamicSharedMemorySize, SMEM_BYTES);
    attn_fused_kernel<<<n_bh, 256, SMEM_BYTES>>>(x, wq, bq, wk, bk, wv, bv, out);
}

// round 2
// speedup vs baseline: 1.0668x; 1.0668x over previous
#include <cuda_runtime.h>
#include <cstdint>

// SelfAttentionLayer fused kernel, round 2: packed f32x2 FMA (FFMA2) everywhere.
//   Q = X Wq + bq ; K = X Wk + bk ; V = X Wv + bv        (X = x[b,h] : [64,256])
//   S[w][v] = sum_c K[w][c] * Q[v][c]   (NO 1/sqrt(d) scale)
//   P = softmax over v ; O = P V ; out = O * X

#define Wn 64
#define Cn 256
#define XS 260   // padded row stride (floats) for 64x256 smem tiles
#define SS 68    // padded row stride for the 64x64 score tile

#define SMEM_FLOATS (3 * Wn * XS + Wn * SS)
#define SMEM_BYTES  (SMEM_FLOATS * 4)

typedef unsigned long long u64;

#define FMA2(D, A, B, C) \
    asm("fma.rn.f32x2 %0, %1, %2, %3;" : "=l"(D) : "l"(A), "l"(B), "l"(C))
#define ADD2(D, A, B) \
    asm("add.rn.f32x2 %0, %1, %2;" : "=l"(D) : "l"(A), "l"(B))

__device__ __forceinline__ u64 pk2(float lo, float hi) {
    u64 r;
    asm("mov.b64 %0, {%1, %2};" : "=l"(r) : "f"(lo), "f"(hi));
    return r;
}
__device__ __forceinline__ float2 upk2(u64 v) {
    float2 f;
    asm("mov.b64 {%0, %1}, %2;" : "=f"(f.x), "=f"(f.y) : "l"(v));
    return f;
}

// ACC[0..3] (packed pairs, 8 channels) += dup(xv) * {WA.x, WA.y, WB.x, WB.y}
#define FMA8P(ACC, XX, WA, WB)            \
    do {                                  \
        FMA2(ACC[0], XX, (WA).x, ACC[0]); \
        FMA2(ACC[1], XX, (WA).y, ACC[1]); \
        FMA2(ACC[2], XX, (WB).x, ACC[2]); \
        FMA2(ACC[3], XX, (WB).y, ACC[3]); \
    } while (0)

// dst[64,256](+pad) = sX[64,256](+pad) @ W[256,256] + bias; 8 rows x 8 cols per thread,
// accumulators are 4 packed f32x2 pairs per row.
__device__ __forceinline__ void proj_gemm(
    const float* __restrict__ sX, float* __restrict__ dst,
    const float* __restrict__ W, const float* __restrict__ bias,
    int r0, int c0)
{
    u64 acc[8][4];
#pragma unroll
    for (int i = 0; i < 8; i++)
#pragma unroll
        for (int j = 0; j < 4; j++) acc[i][j] = 0ULL;

#pragma unroll 2
    for (int k = 0; k < Cn; k += 4) {
        float4 xf[8];
#pragma unroll
        for (int r = 0; r < 8; r++)
            xf[r] = *reinterpret_cast<const float4*>(&sX[(r0 + r) * XS + k]);  // warp broadcast

        ulonglong2 wA[4], wB[4];   // packed channel pairs (c0..c0+3), (c0+4..c0+7)
#pragma unroll
        for (int kk = 0; kk < 4; kk++) {
            wA[kk] = *reinterpret_cast<const ulonglong2*>(&W[(size_t)(k + kk) * Cn + c0]);
            wB[kk] = *reinterpret_cast<const ulonglong2*>(&W[(size_t)(k + kk) * Cn + c0 + 4]);
        }

#pragma unroll
        for (int kk = 0; kk < 4; kk++) {
#pragma unroll
            for (int r = 0; r < 8; r++) {
                float xv = (kk == 0) ? xf[r].x : (kk == 1) ? xf[r].y
                         : (kk == 2) ? xf[r].z : xf[r].w;
                u64 xx = pk2(xv, xv);
                FMA8P(acc[r], xx, wA[kk], wB[kk]);
            }
        }
    }

    ulonglong2 bA = *reinterpret_cast<const ulonglong2*>(&bias[c0]);
    ulonglong2 bB = *reinterpret_cast<const ulonglong2*>(&bias[c0 + 4]);
#pragma unroll
    for (int r = 0; r < 8; r++) {
        ADD2(acc[r][0], acc[r][0], bA.x);
        ADD2(acc[r][1], acc[r][1], bA.y);
        ADD2(acc[r][2], acc[r][2], bB.x);
        ADD2(acc[r][3], acc[r][3], bB.y);
        ulonglong2 o0; o0.x = acc[r][0]; o0.y = acc[r][1];
        ulonglong2 o1; o1.x = acc[r][2]; o1.y = acc[r][3];
        *reinterpret_cast<ulonglong2*>(&dst[(r0 + r) * XS + c0])     = o0;
        *reinterpret_cast<ulonglong2*>(&dst[(r0 + r) * XS + c0 + 4]) = o1;
    }
}

__global__ void __launch_bounds__(256, 1)
attn_fused_kernel(const float* __restrict__ x,
                  const float* __restrict__ wq, const float* __restrict__ bq,
                  const float* __restrict__ wk, const float* __restrict__ bk,
                  const float* __restrict__ wv, const float* __restrict__ bv,
                  float* __restrict__ out)
{
    extern __shared__ float smem[];
    float* sX  = smem;                 // [64][260] raw input tile (kept for the gate)
    float* sQ  = sX  + Wn * XS;        // [64][260] Q
    float* sKV = sQ  + Wn * XS;        // [64][260] K, later overwritten with V
    float* sS  = sKV + Wn * XS;        // [64][68]  scores -> probabilities

    const int tid = threadIdx.x;
    const size_t bh = blockIdx.x;
    const float* xg = x   + bh * (size_t)(Wn * Cn);
    float*       og = out + bh * (size_t)(Wn * Cn);

    // ---- P0: stage X ----
    for (int i = tid; i < Wn * Cn / 4; i += 256) {
        int r = i >> 6;
        int c = (i & 63) << 2;
        float4 v = reinterpret_cast<const float4*>(xg)[i];
        *reinterpret_cast<float4*>(&sX[r * XS + c]) = v;
    }
    __syncthreads();

    const int rtile = tid >> 5;    // warp id, 0..7
    const int ctile = tid & 31;    // lane
    const int r0 = rtile << 3;
    const int c0 = ctile << 3;

    // ---- P1: Q and K projections ----
    proj_gemm(sX, sQ,  wq, bq, r0, c0);
    proj_gemm(sX, sKV, wk, bk, r0, c0);
    __syncthreads();

    // ---- P2: S = K Q^T ; packed along the contraction dim (no dup needed) ----
    {
        const int v0 = r0;         // this warp's q-row block
        const int w0 = ctile;
        u64 a0[8][2], a1[8][2];
#pragma unroll
        for (int j = 0; j < 8; j++) {
            a0[j][0] = a0[j][1] = 0ULL;
            a1[j][0] = a1[j][1] = 0ULL;
        }

#pragma unroll 2
        for (int c = 0; c < Cn; c += 4) {
            ulonglong2 k0 = *reinterpret_cast<const ulonglong2*>(&sKV[w0 * XS + c]);
            ulonglong2 k1 = *reinterpret_cast<const ulonglong2*>(&sKV[(w0 + 32) * XS + c]);
#pragma unroll
            for (int j = 0; j < 8; j++) {
                ulonglong2 q = *reinterpret_cast<const ulonglong2*>(&sQ[(v0 + j) * XS + c]);
                FMA2(a0[j][0], k0.x, q.x, a0[j][0]);
                FMA2(a0[j][1], k0.y, q.y, a0[j][1]);
                FMA2(a1[j][0], k1.x, q.x, a1[j][0]);
                FMA2(a1[j][1], k1.y, q.y, a1[j][1]);
            }
        }

        float s0[8], s1[8];
#pragma unroll
        for (int j = 0; j < 8; j++) {
            float2 p00 = upk2(a0[j][0]), p01 = upk2(a0[j][1]);
            float2 p10 = upk2(a1[j][0]), p11 = upk2(a1[j][1]);
            s0[j] = (p00.x + p00.y) + (p01.x + p01.y);
            s1[j] = (p10.x + p10.y) + (p11.x + p11.y);
        }
        *reinterpret_cast<float4*>(&sS[w0 * SS + v0])            = make_float4(s0[0], s0[1], s0[2], s0[3]);
        *reinterpret_cast<float4*>(&sS[w0 * SS + v0 + 4])        = make_float4(s0[4], s0[5], s0[6], s0[7]);
        *reinterpret_cast<float4*>(&sS[(w0 + 32) * SS + v0])     = make_float4(s1[0], s1[1], s1[2], s1[3]);
        *reinterpret_cast<float4*>(&sS[(w0 + 32) * SS + v0 + 4]) = make_float4(s1[4], s1[5], s1[6], s1[7]);
    }
    __syncthreads();

    // ---- P3: row softmax over v (warp handles rows r0..r0+7) ----
    {
        const int lane = ctile;
#pragma unroll
        for (int rr = 0; rr < 8; rr++) {
            int r = r0 + rr;
            float aa = sS[r * SS + lane];
            float bb = sS[r * SS + lane + 32];
            float m = fmaxf(aa, bb);
#pragma unroll
            for (int off = 16; off > 0; off >>= 1)
                m = fmaxf(m, __shfl_xor_sync(0xffffffffu, m, off));
            float e0 = __expf(aa - m);
            float e1 = __expf(bb - m);
            float s = e0 + e1;
#pragma unroll
            for (int off = 16; off > 0; off >>= 1)
                s += __shfl_xor_sync(0xffffffffu, s, off);
            float inv = 1.0f / s;
            sS[r * SS + lane]      = e0 * inv;
            sS[r * SS + lane + 32] = e1 * inv;
        }
    }

    // ---- P4: V projection (overwrites K buffer; P2 reads done before last sync) ----
    proj_gemm(sX, sKV, wv, bv, r0, c0);
    __syncthreads();

    // ---- P5: O = P V (packed along channels), gate with X, store ----
    {
        u64 acc[8][4];
#pragma unroll
        for (int i = 0; i < 8; i++)
#pragma unroll
            for (int j = 0; j < 4; j++) acc[i][j] = 0ULL;

#pragma unroll 2
        for (int v = 0; v < Wn; v += 4) {
            float4 pf[8];
#pragma unroll
            for (int r = 0; r < 8; r++)
                pf[r] = *reinterpret_cast<const float4*>(&sS[(r0 + r) * SS + v]); // broadcast

            ulonglong2 va[4], vb[4];
#pragma unroll
            for (int vv = 0; vv < 4; vv++) {
                va[vv] = *reinterpret_cast<const ulonglong2*>(&sKV[(v + vv) * XS + c0]);
                vb[vv] = *reinterpret_cast<const ulonglong2*>(&sKV[(v + vv) * XS + c0 + 4]);
            }
#pragma unroll
            for (int vv = 0; vv < 4; vv++) {
#pragma unroll
                for (int r = 0; r < 8; r++) {
                    float p = (vv == 0) ? pf[r].x : (vv == 1) ? pf[r].y
                            : (vv == 2) ? pf[r].z : pf[r].w;
                    u64 pp = pk2(p, p);
                    FMA8P(acc[r], pp, va[vv], vb[vv]);
                }
            }
        }

#pragma unroll
        for (int r = 0; r < 8; r++) {
            float4 x0 = *reinterpret_cast<const float4*>(&sX[(r0 + r) * XS + c0]);
            float4 x1 = *reinterpret_cast<const float4*>(&sX[(r0 + r) * XS + c0 + 4]);
            float2 a0 = upk2(acc[r][0]), a1 = upk2(acc[r][1]);
            float2 a2 = upk2(acc[r][2]), a3 = upk2(acc[r][3]);
            float4 o0 = make_float4(a0.x * x0.x, a0.y * x0.y, a1.x * x0.z, a1.y * x0.w);
            float4 o1 = make_float4(a2.x * x1.x, a2.y * x1.y, a3.x * x1.z, a3.y * x1.w);
            *reinterpret_cast<float4*>(&og[(r0 + r) * Cn + c0])     = o0;
            *reinterpret_cast<float4*>(&og[(r0 + r) * Cn + c0 + 4]) = o1;
        }
    }
}

extern "C" void kernel_launch(void* const* d_in, const int* in_sizes, int n_in,
                              void* d_out, int out_size)
{
    const float* x  = (const float*)d_in[0];
    const float* wq = (const float*)d_in[1];
    const float* bq = (const float*)d_in[2];
    const float* wk = (const float*)d_in[3];
    const float* bk = (const float*)d_in[4];
    const float* wv = (const float*)d_in[5];
    const float* bv = (const float*)d_in[6];
    float* out = (float*)d_out;

    int n_bh = in_sizes[0] / (Wn * Cn);   // B*H = 2048

    cudaFuncSetAttribute(attn_fused_kernel,
                         cudaFuncAttributeMaxDynamicSharedMemorySize, SMEM_BYTES);
    attn_fused_kernel<<<n_bh, 256, SMEM_BYTES>>>(x, wq, bq, wk, bk, wv, bv, out);
}

// round 3
// speedup vs baseline: 1.0690x; 1.0020x over previous
#include <cuda_runtime.h>
#include <cstdint>

// SelfAttentionLayer fused kernel, round 2: packed f32x2 FMA (FFMA2) everywhere.
//   Q = X Wq + bq ; K = X Wk + bk ; V = X Wv + bv        (X = x[b,h] : [64,256])
//   S[w][v] = sum_c K[w][c] * Q[v][c]   (NO 1/sqrt(d) scale)
//   P = softmax over v ; O = P V ; out = O * X

#define Wn 64
#define Cn 256
#define XS 260   // padded row stride (floats) for 64x256 smem tiles
#define SS 68    // padded row stride for the 64x64 score tile

#define SMEM_FLOATS (3 * Wn * XS + Wn * SS)
#define SMEM_BYTES  (SMEM_FLOATS * 4)

typedef unsigned long long u64;

#define FMA2(D, A, B, C) \
    asm("fma.rn.f32x2 %0, %1, %2, %3;" : "=l"(D) : "l"(A), "l"(B), "l"(C))
#define ADD2(D, A, B) \
    asm("add.rn.f32x2 %0, %1, %2;" : "=l"(D) : "l"(A), "l"(B))

__device__ __forceinline__ u64 pk2(float lo, float hi) {
    u64 r;
    asm("mov.b64 %0, {%1, %2};" : "=l"(r) : "f"(lo), "f"(hi));
    return r;
}
__device__ __forceinline__ float2 upk2(u64 v) {
    float2 f;
    asm("mov.b64 {%0, %1}, %2;" : "=f"(f.x), "=f"(f.y) : "l"(v));
    return f;
}

// ACC[0..3] (packed pairs, 8 channels) += dup(xv) * {WA.x, WA.y, WB.x, WB.y}
#define FMA8P(ACC, XX, WA, WB)            \
    do {                                  \
        FMA2(ACC[0], XX, (WA).x, ACC[0]); \
        FMA2(ACC[1], XX, (WA).y, ACC[1]); \
        FMA2(ACC[2], XX, (WB).x, ACC[2]); \
        FMA2(ACC[3], XX, (WB).y, ACC[3]); \
    } while (0)

// dst[64,256](+pad) = sX[64,256](+pad) @ W[256,256] + bias; 8 rows x 8 cols per thread,
// accumulators are 4 packed f32x2 pairs per row.
__device__ __forceinline__ void proj_gemm(
    const float* __restrict__ sX, float* __restrict__ dst,
    const float* __restrict__ W, const float* __restrict__ bias,
    int r0, int c0)
{
    u64 acc[8][4];
#pragma unroll
    for (int i = 0; i < 8; i++)
#pragma unroll
        for (int j = 0; j < 4; j++) acc[i][j] = 0ULL;

#pragma unroll 2
    for (int k = 0; k < Cn; k += 4) {
        float4 xf[8];
#pragma unroll
        for (int r = 0; r < 8; r++)
            xf[r] = *reinterpret_cast<const float4*>(&sX[(r0 + r) * XS + k]);  // warp broadcast

        ulonglong2 wA[4], wB[4];   // packed channel pairs (c0..c0+3), (c0+4..c0+7)
#pragma unroll
        for (int kk = 0; kk < 4; kk++) {
            wA[kk] = *reinterpret_cast<const ulonglong2*>(&W[(size_t)(k + kk) * Cn + c0]);
            wB[kk] = *reinterpret_cast<const ulonglong2*>(&W[(size_t)(k + kk) * Cn + c0 + 4]);
        }

#pragma unroll
        for (int kk = 0; kk < 4; kk++) {
#pragma unroll
            for (int r = 0; r < 8; r++) {
                float xv = (kk == 0) ? xf[r].x : (kk == 1) ? xf[r].y
                         : (kk == 2) ? xf[r].z : xf[r].w;
                u64 xx = pk2(xv, xv);
                FMA8P(acc[r], xx, wA[kk], wB[kk]);
            }
        }
    }

    ulonglong2 bA = *reinterpret_cast<const ulonglong2*>(&bias[c0]);
    ulonglong2 bB = *reinterpret_cast<const ulonglong2*>(&bias[c0 + 4]);
#pragma unroll
    for (int r = 0; r < 8; r++) {
        ADD2(acc[r][0], acc[r][0], bA.x);
        ADD2(acc[r][1], acc[r][1], bA.y);
        ADD2(acc[r][2], acc[r][2], bB.x);
        ADD2(acc[r][3], acc[r][3], bB.y);
        ulonglong2 o0; o0.x = acc[r][0]; o0.y = acc[r][1];
        ulonglong2 o1; o1.x = acc[r][2]; o1.y = acc[r][3];
        *reinterpret_cast<ulonglong2*>(&dst[(r0 + r) * XS + c0])     = o0;
        *reinterpret_cast<ulonglong2*>(&dst[(r0 + r) * XS + c0 + 4]) = o1;
    }
}

__global__ void __launch_bounds__(256, 1)
attn_fused_kernel(const float* __restrict__ x,
                  const float* __restrict__ wq, const float* __restrict__ bq,
                  const float* __restrict__ wk, const float* __restrict__ bk,
                  const float* __restrict__ wv, const float* __restrict__ bv,
                  float* __restrict__ out)
{
    extern __shared__ float smem[];
    float* sX  = smem;                 // [64][260] raw input tile (kept for the gate)
    float* sQ  = sX  + Wn * XS;        // [64][260] Q
    float* sKV = sQ  + Wn * XS;        // [64][260] K, later overwritten with V
    float* sS  = sKV + Wn * XS;        // [64][68]  scores -> probabilities

    const int tid = threadIdx.x;
    const size_t bh = blockIdx.x;
    const float* xg = x   + bh * (size_t)(Wn * Cn);
    float*       og = out + bh * (size_t)(Wn * Cn);

    // ---- P0: stage X ----
    for (int i = tid; i < Wn * Cn / 4; i += 256) {
        int r = i >> 6;
        int c = (i & 63) << 2;
        float4 v = reinterpret_cast<const float4*>(xg)[i];
        *reinterpret_cast<float4*>(&sX[r * XS + c]) = v;
    }
    __syncthreads();

    const int rtile = tid >> 5;    // warp id, 0..7
    const int ctile = tid & 31;    // lane
    const int r0 = rtile << 3;
    const int c0 = ctile << 3;

    // ---- P1: Q and K projections ----
    proj_gemm(sX, sQ,  wq, bq, r0, c0);
    proj_gemm(sX, sKV, wk, bk, r0, c0);
    __syncthreads();

    // ---- P2: S = K Q^T ; packed along the contraction dim (no dup needed) ----
    {
        const int v0 = r0;         // this warp's q-row block
        const int w0 = ctile;
        u64 a0[8][2], a1[8][2];
#pragma unroll
        for (int j = 0; j < 8; j++) {
            a0[j][0] = a0[j][1] = 0ULL;
            a1[j][0] = a1[j][1] = 0ULL;
        }

#pragma unroll 2
        for (int c = 0; c < Cn; c += 4) {
            ulonglong2 k0 = *reinterpret_cast<const ulonglong2*>(&sKV[w0 * XS + c]);
            ulonglong2 k1 = *reinterpret_cast<const ulonglong2*>(&sKV[(w0 + 32) * XS + c]);
#pragma unroll
            for (int j = 0; j < 8; j++) {
                ulonglong2 q = *reinterpret_cast<const ulonglong2*>(&sQ[(v0 + j) * XS + c]);
                FMA2(a0[j][0], k0.x, q.x, a0[j][0]);
                FMA2(a0[j][1], k0.y, q.y, a0[j][1]);
                FMA2(a1[j][0], k1.x, q.x, a1[j][0]);
                FMA2(a1[j][1], k1.y, q.y, a1[j][1]);
            }
        }

        float s0[8], s1[8];
#pragma unroll
        for (int j = 0; j < 8; j++) {
            float2 p00 = upk2(a0[j][0]), p01 = upk2(a0[j][1]);
            float2 p10 = upk2(a1[j][0]), p11 = upk2(a1[j][1]);
            s0[j] = (p00.x + p00.y) + (p01.x + p01.y);
            s1[j] = (p10.x + p10.y) + (p11.x + p11.y);
        }
        *reinterpret_cast<float4*>(&sS[w0 * SS + v0])            = make_float4(s0[0], s0[1], s0[2], s0[3]);
        *reinterpret_cast<float4*>(&sS[w0 * SS + v0 + 4])        = make_float4(s0[4], s0[5], s0[6], s0[7]);
        *reinterpret_cast<float4*>(&sS[(w0 + 32) * SS + v0])     = make_float4(s1[0], s1[1], s1[2], s1[3]);
        *reinterpret_cast<float4*>(&sS[(w0 + 32) * SS + v0 + 4]) = make_float4(s1[4], s1[5], s1[6], s1[7]);
    }
    __syncthreads();

    // ---- P3: row softmax over v (warp handles rows r0..r0+7) ----
    {
        const int lane = ctile;
#pragma unroll
        for (int rr = 0; rr < 8; rr++) {
            int r = r0 + rr;
            float aa = sS[r * SS + lane];
            float bb = sS[r * SS + lane + 32];
            float m = fmaxf(aa, bb);
#pragma unroll
            for (int off = 16; off > 0; off >>= 1)
                m = fmaxf(m, __shfl_xor_sync(0xffffffffu, m, off));
            float e0 = __expf(aa - m);
            float e1 = __expf(bb - m);
            float s = e0 + e1;
#pragma unroll
            for (int off = 16; off > 0; off >>= 1)
                s += __shfl_xor_sync(0xffffffffu, s, off);
            float inv = 1.0f / s;
            sS[r * SS + lane]      = e0 * inv;
            sS[r * SS + lane + 32] = e1 * inv;
        }
    }

    // ---- P4: V projection (overwrites K buffer; P2 reads done before last sync) ----
    proj_gemm(sX, sKV, wv, bv, r0, c0);
    __syncthreads();

    // ---- P5: O = P V (packed along channels), gate with X, store ----
    {
        u64 acc[8][4];
#pragma unroll
        for (int i = 0; i < 8; i++)
#pragma unroll
            for (int j = 0; j < 4; j++) acc[i][j] = 0ULL;

#pragma unroll 2
        for (int v = 0; v < Wn; v += 4) {
            float4 pf[8];
#pragma unroll
            for (int r = 0; r < 8; r++)
                pf[r] = *reinterpret_cast<const float4*>(&sS[(r0 + r) * SS + v]); // broadcast

            ulonglong2 va[4], vb[4];
#pragma unroll
            for (int vv = 0; vv < 4; vv++) {
                va[vv] = *reinterpret_cast<const ulonglong2*>(&sKV[(v + vv) * XS + c0]);
                vb[vv] = *reinterpret_cast<const ulonglong2*>(&sKV[(v + vv) * XS + c0 + 4]);
            }
#pragma unroll
            for (int vv = 0; vv < 4; vv++) {
#pragma unroll
                for (int r = 0; r < 8; r++) {
                    float p = (vv == 0) ? pf[r].x : (vv == 1) ? pf[r].y
                            : (vv == 2) ? pf[r].z : pf[r].w;
                    u64 pp = pk2(p, p);
                    FMA8P(acc[r], pp, va[vv], vb[vv]);
                }
            }
        }

#pragma unroll
        for (int r = 0; r < 8; r++) {
            float4 x0 = *reinterpret_cast<const float4*>(&sX[(r0 + r) * XS + c0]);
            float4 x1 = *reinterpret_cast<const float4*>(&sX[(r0 + r) * XS + c0 + 4]);
            float2 a0 = upk2(acc[r][0]), a1 = upk2(acc[r][1]);
            float2 a2 = upk2(acc[r][2]), a3 = upk2(acc[r][3]);
            float4 o0 = make_float4(a0.x * x0.x, a0.y * x0.y, a1.x * x0.z, a1.y * x0.w);
            float4 o1 = make_float4(a2.x * x1.x, a2.y * x1.y, a3.x * x1.z, a3.y * x1.w);
            *reinterpret_cast<float4*>(&og[(r0 + r) * Cn + c0])     = o0;
            *reinterpret_cast<float4*>(&og[(r0 + r) * Cn + c0 + 4]) = o1;
        }
    }
}

extern "C" void kernel_launch(void* const* d_in, const int* in_sizes, int n_in,
                              void* d_out, int out_size)
{
    const float* x  = (const float*)d_in[0];
    const float* wq = (const float*)d_in[1];
    const float* bq = (const float*)d_in[2];
    const float* wk = (const float*)d_in[3];
    const float* bk = (const float*)d_in[4];
    const float* wv = (const float*)d_in[5];
    const float* bv = (const float*)d_in[6];
    float* out = (float*)d_out;

    int n_bh = in_sizes[0] / (Wn * Cn);   // B*H = 2048

    cudaFuncSetAttribute(attn_fused_kernel,
                         cudaFuncAttributeMaxDynamicSharedMemorySize, SMEM_BYTES);
    attn_fused_kernel<<<n_bh, 256, SMEM_BYTES>>>(x, wq, bq, wk, bk, wv, bv, out);
}

// round 4
// speedup vs baseline: 1.1889x; 1.1122x over previous
#include <cuda_runtime.h>
#include <cstdint>

// SelfAttentionLayer fused kernel, round 3: FFMA2 + interleaved column ownership
// so every weight LDG.128 is warp-contiguous (4 lines instead of 8 half-used lines).
//   Q = X Wq + bq ; K = X Wk + bk ; V = X Wv + bv        (X = x[b,h] : [64,256])
//   S[w][v] = sum_c K[w][c] * Q[v][c]   (NO 1/sqrt(d) scale)
//   P = softmax over v ; O = P V ; out = O * X

#define Wn 64
#define Cn 256
#define XS 260   // padded row stride (floats); 260/4=65 odd mod 8 -> conflict-free row-varying .128
#define SS 68    // padded row stride for the 64x64 score tile

#define SMEM_FLOATS (3 * Wn * XS + Wn * SS)
#define SMEM_BYTES  (SMEM_FLOATS * 4)

typedef unsigned long long u64;

#define FMA2(D, A, B, C) \
    asm("fma.rn.f32x2 %0, %1, %2, %3;" : "=l"(D) : "l"(A), "l"(B), "l"(C))
#define ADD2(D, A, B) \
    asm("add.rn.f32x2 %0, %1, %2;" : "=l"(D) : "l"(A), "l"(B))

__device__ __forceinline__ u64 pk2(float lo, float hi) {
    u64 r;
    asm("mov.b64 %0, {%1, %2};" : "=l"(r) : "f"(lo), "f"(hi));
    return r;
}
__device__ __forceinline__ float2 upk2(u64 v) {
    float2 f;
    asm("mov.b64 {%0, %1}, %2;" : "=f"(f.x), "=f"(f.y) : "l"(v));
    return f;
}

// ACC[0..3] (packed pairs: cols {cA..cA+3}, {cB..cB+3}) += dup(xv) * {WA.x,WA.y,WB.x,WB.y}
#define FMA8P(ACC, XX, WA, WB)            \
    do {                                  \
        FMA2(ACC[0], XX, (WA).x, ACC[0]); \
        FMA2(ACC[1], XX, (WA).y, ACC[1]); \
        FMA2(ACC[2], XX, (WB).x, ACC[2]); \
        FMA2(ACC[3], XX, (WB).y, ACC[3]); \
    } while (0)

// dst[64,256](+pad) = sX[64,256](+pad) @ W[256,256] + bias.
// Thread owns rows r0..r0+7 and column groups [cA,cA+4) and [cB,cB+4) (cB = cA+128).
__device__ __forceinline__ void proj_gemm(
    const float* __restrict__ sX, float* __restrict__ dst,
    const float* __restrict__ W, const float* __restrict__ bias,
    int r0, int cA)
{
    const int cB = cA + 128;
    u64 acc[8][4];
#pragma unroll
    for (int i = 0; i < 8; i++)
#pragma unroll
        for (int j = 0; j < 4; j++) acc[i][j] = 0ULL;

#pragma unroll 2
    for (int k = 0; k < Cn; k += 4) {
        float4 xf[8];
#pragma unroll
        for (int r = 0; r < 8; r++)
            xf[r] = *reinterpret_cast<const float4*>(&sX[(r0 + r) * XS + k]);  // warp broadcast

        ulonglong2 wA[4], wB[4];   // 16B each; warp-contiguous 512B per load
#pragma unroll
        for (int kk = 0; kk < 4; kk++) {
            wA[kk] = *reinterpret_cast<const ulonglong2*>(&W[(size_t)(k + kk) * Cn + cA]);
            wB[kk] = *reinterpret_cast<const ulonglong2*>(&W[(size_t)(k + kk) * Cn + cB]);
        }

#pragma unroll
        for (int kk = 0; kk < 4; kk++) {
#pragma unroll
            for (int r = 0; r < 8; r++) {
                float xv = (kk == 0) ? xf[r].x : (kk == 1) ? xf[r].y
                         : (kk == 2) ? xf[r].z : xf[r].w;
                u64 xx = pk2(xv, xv);
                FMA8P(acc[r], xx, wA[kk], wB[kk]);
            }
        }
    }

    ulonglong2 bA = *reinterpret_cast<const ulonglong2*>(&bias[cA]);
    ulonglong2 bB = *reinterpret_cast<const ulonglong2*>(&bias[cB]);
#pragma unroll
    for (int r = 0; r < 8; r++) {
        ADD2(acc[r][0], acc[r][0], bA.x);
        ADD2(acc[r][1], acc[r][1], bA.y);
        ADD2(acc[r][2], acc[r][2], bB.x);
        ADD2(acc[r][3], acc[r][3], bB.y);
        ulonglong2 oA; oA.x = acc[r][0]; oA.y = acc[r][1];
        ulonglong2 oB; oB.x = acc[r][2]; oB.y = acc[r][3];
        *reinterpret_cast<ulonglong2*>(&dst[(r0 + r) * XS + cA]) = oA;
        *reinterpret_cast<ulonglong2*>(&dst[(r0 + r) * XS + cB]) = oB;
    }
}

__global__ void __launch_bounds__(256, 1)
attn_fused_kernel(const float* __restrict__ x,
                  const float* __restrict__ wq, const float* __restrict__ bq,
                  const float* __restrict__ wk, const float* __restrict__ bk,
                  const float* __restrict__ wv, const float* __restrict__ bv,
                  float* __restrict__ out)
{
    extern __shared__ float smem[];
    float* sX  = smem;                 // [64][260] raw input tile (kept for the gate)
    float* sQ  = sX  + Wn * XS;        // [64][260] Q
    float* sKV = sQ  + Wn * XS;        // [64][260] K, later overwritten with V
    float* sS  = sKV + Wn * XS;        // [64][68]  scores -> probabilities

    const int tid = threadIdx.x;
    const size_t bh = blockIdx.x;
    const float* xg = x   + bh * (size_t)(Wn * Cn);
    float*       og = out + bh * (size_t)(Wn * Cn);

    // ---- P0: stage X ----
    for (int i = tid; i < Wn * Cn / 4; i += 256) {
        int r = i >> 6;
        int c = (i & 63) << 2;
        float4 v = reinterpret_cast<const float4*>(xg)[i];
        *reinterpret_cast<float4*>(&sX[r * XS + c]) = v;
    }
    __syncthreads();

    const int rtile = tid >> 5;    // warp id, 0..7
    const int lane  = tid & 31;
    const int r0 = rtile << 3;
    const int cA = lane << 2;      // cols [cA, cA+4) and [cA+128, cA+132)

    // ---- P1: Q and K projections ----
    proj_gemm(sX, sQ,  wq, bq, r0, cA);
    proj_gemm(sX, sKV, wk, bk, r0, cA);
    __syncthreads();

    // ---- P2: S = K Q^T ; packed along the contraction dim ----
    {
        const int v0 = r0;         // this warp's q-row block
        const int w0 = lane;
        u64 a0[8][2], a1[8][2];
#pragma unroll
        for (int j = 0; j < 8; j++) {
            a0[j][0] = a0[j][1] = 0ULL;
            a1[j][0] = a1[j][1] = 0ULL;
        }

#pragma unroll 2
        for (int c = 0; c < Cn; c += 4) {
            ulonglong2 k0 = *reinterpret_cast<const ulonglong2*>(&sKV[w0 * XS + c]);
            ulonglong2 k1 = *reinterpret_cast<const ulonglong2*>(&sKV[(w0 + 32) * XS + c]);
#pragma unroll
            for (int j = 0; j < 8; j++) {
                ulonglong2 q = *reinterpret_cast<const ulonglong2*>(&sQ[(v0 + j) * XS + c]);
                FMA2(a0[j][0], k0.x, q.x, a0[j][0]);
                FMA2(a0[j][1], k0.y, q.y, a0[j][1]);
                FMA2(a1[j][0], k1.x, q.x, a1[j][0]);
                FMA2(a1[j][1], k1.y, q.y, a1[j][1]);
            }
        }

        float s0[8], s1[8];
#pragma unroll
        for (int j = 0; j < 8; j++) {
            float2 p00 = upk2(a0[j][0]), p01 = upk2(a0[j][1]);
            float2 p10 = upk2(a1[j][0]), p11 = upk2(a1[j][1]);
            s0[j] = (p00.x + p00.y) + (p01.x + p01.y);
            s1[j] = (p10.x + p10.y) + (p11.x + p11.y);
        }
        *reinterpret_cast<float4*>(&sS[w0 * SS + v0])            = make_float4(s0[0], s0[1], s0[2], s0[3]);
        *reinterpret_cast<float4*>(&sS[w0 * SS + v0 + 4])        = make_float4(s0[4], s0[5], s0[6], s0[7]);
        *reinterpret_cast<float4*>(&sS[(w0 + 32) * SS + v0])     = make_float4(s1[0], s1[1], s1[2], s1[3]);
        *reinterpret_cast<float4*>(&sS[(w0 + 32) * SS + v0 + 4]) = make_float4(s1[4], s1[5], s1[6], s1[7]);
    }
    __syncthreads();

    // ---- P3: row softmax over v (warp handles rows r0..r0+7) ----
    {
#pragma unroll
        for (int rr = 0; rr < 8; rr++) {
            int r = r0 + rr;
            float aa = sS[r * SS + lane];
            float bb = sS[r * SS + lane + 32];
            float m = fmaxf(aa, bb);
#pragma unroll
            for (int off = 16; off > 0; off >>= 1)
                m = fmaxf(m, __shfl_xor_sync(0xffffffffu, m, off));
            float e0 = __expf(aa - m);
            float e1 = __expf(bb - m);
            float s = e0 + e1;
#pragma unroll
            for (int off = 16; off > 0; off >>= 1)
                s += __shfl_xor_sync(0xffffffffu, s, off);
            float inv = 1.0f / s;
            sS[r * SS + lane]      = e0 * inv;
            sS[r * SS + lane + 32] = e1 * inv;
        }
    }

    // ---- P4: V projection (overwrites K buffer; P2 reads done before last sync) ----
    proj_gemm(sX, sKV, wv, bv, r0, cA);
    __syncthreads();

    // ---- P5: O = P V (packed along channels), gate with X, store ----
    {
        const int cB = cA + 128;
        u64 acc[8][4];
#pragma unroll
        for (int i = 0; i < 8; i++)
#pragma unroll
            for (int j = 0; j < 4; j++) acc[i][j] = 0ULL;

#pragma unroll 2
        for (int v = 0; v < Wn; v += 4) {
            float4 pf[8];
#pragma unroll
            for (int r = 0; r < 8; r++)
                pf[r] = *reinterpret_cast<const float4*>(&sS[(r0 + r) * SS + v]); // broadcast

            ulonglong2 va[4], vb[4];
#pragma unroll
            for (int vv = 0; vv < 4; vv++) {
                va[vv] = *reinterpret_cast<const ulonglong2*>(&sKV[(v + vv) * XS + cA]);
                vb[vv] = *reinterpret_cast<const ulonglong2*>(&sKV[(v + vv) * XS + cB]);
            }
#pragma unroll
            for (int vv = 0; vv < 4; vv++) {
#pragma unroll
                for (int r = 0; r < 8; r++) {
                    float p = (vv == 0) ? pf[r].x : (vv == 1) ? pf[r].y
                            : (vv == 2) ? pf[r].z : pf[r].w;
                    u64 pp = pk2(p, p);
                    FMA8P(acc[r], pp, va[vv], vb[vv]);
                }
            }
        }

#pragma unroll
        for (int r = 0; r < 8; r++) {
            float4 x0 = *reinterpret_cast<const float4*>(&sX[(r0 + r) * XS + cA]);
            float4 x1 = *reinterpret_cast<const float4*>(&sX[(r0 + r) * XS + cB]);
            float2 a0 = upk2(acc[r][0]), a1 = upk2(acc[r][1]);
            float2 a2 = upk2(acc[r][2]), a3 = upk2(acc[r][3]);
            float4 o0 = make_float4(a0.x * x0.x, a0.y * x0.y, a1.x * x0.z, a1.y * x0.w);
            float4 o1 = make_float4(a2.x * x1.x, a2.y * x1.y, a3.x * x1.z, a3.y * x1.w);
            *reinterpret_cast<float4*>(&og[(r0 + r) * Cn + cA]) = o0;
            *reinterpret_cast<float4*>(&og[(r0 + r) * Cn + cB]) = o1;
        }
    }
}

extern "C" void kernel_launch(void* const* d_in, const int* in_sizes, int n_in,
                              void* d_out, int out_size)
{
    const float* x  = (const float*)d_in[0];
    const float* wq = (const float*)d_in[1];
    const float* bq = (const float*)d_in[2];
    const float* wk = (const float*)d_in[3];
    const float* bk = (const float*)d_in[4];
    const float* wv = (const float*)d_in[5];
    const float* bv = (const float*)d_in[6];
    float* out = (float*)d_out;

    int n_bh = in_sizes[0] / (Wn * Cn);   // B*H = 2048

    cudaFuncSetAttribute(attn_fused_kernel,
                         cudaFuncAttributeMaxDynamicSharedMemorySize, SMEM_BYTES);
    attn_fused_kernel<<<n_bh, 256, SMEM_BYTES>>>(x, wq, bq, wk, bk, wv, bv, out);
}

// round 5
// speedup vs baseline: 1.2813x; 1.0777x over previous
#include <cuda_runtime.h>
#include <cstdint>

// SelfAttentionLayer fused kernel, round 4: 512 threads (16 warps) for latency hiding.
// Warp = (row-block, col-slab); weight traffic unchanged, X loads are broadcasts.
//   Q = X Wq + bq ; K = X Wk + bk ; V = X Wv + bv        (X = x[b,h] : [64,256])
//   S[w][v] = sum_c K[w][c] * Q[v][c]   (NO 1/sqrt(d) scale)
//   P = softmax over v ; O = P V ; out = O * X

#define Wn 64
#define Cn 256
#define XS 260   // padded row stride (floats); 260/4=65 odd -> conflict-free row-varying .128
#define SS 68    // padded row stride for the 64x64 score tile

#define SMEM_FLOATS (3 * Wn * XS + Wn * SS)
#define SMEM_BYTES  (SMEM_FLOATS * 4)

#define NTHREADS 512

typedef unsigned long long u64;

#define FMA2(D, A, B, C) \
    asm("fma.rn.f32x2 %0, %1, %2, %3;" : "=l"(D) : "l"(A), "l"(B), "l"(C))
#define ADD2(D, A, B) \
    asm("add.rn.f32x2 %0, %1, %2;" : "=l"(D) : "l"(A), "l"(B))

__device__ __forceinline__ u64 pk2(float lo, float hi) {
    u64 r;
    asm("mov.b64 %0, {%1, %2};" : "=l"(r) : "f"(lo), "f"(hi));
    return r;
}
__device__ __forceinline__ float2 upk2(u64 v) {
    float2 f;
    asm("mov.b64 {%0, %1}, %2;" : "=f"(f.x), "=f"(f.y) : "l"(v));
    return f;
}

// dst[64,256](+pad) = sX @ W + bias. Thread owns rows r0..r0+7, cols [c0, c0+4).
// acc[r] = 2 packed f32x2 pairs (4 channels).
__device__ __forceinline__ void proj_gemm(
    const float* __restrict__ sX, float* __restrict__ dst,
    const float* __restrict__ W, const float* __restrict__ bias,
    int r0, int c0)
{
    u64 acc[8][2];
#pragma unroll
    for (int i = 0; i < 8; i++) { acc[i][0] = 0ULL; acc[i][1] = 0ULL; }

#pragma unroll 2
    for (int k = 0; k < Cn; k += 4) {
        float4 xf[8];
#pragma unroll
        for (int r = 0; r < 8; r++)
            xf[r] = *reinterpret_cast<const float4*>(&sX[(r0 + r) * XS + k]);  // broadcast

        ulonglong2 w[4];   // 16B per lane; warp-contiguous 512B per kk
#pragma unroll
        for (int kk = 0; kk < 4; kk++)
            w[kk] = *reinterpret_cast<const ulonglong2*>(&W[(size_t)(k + kk) * Cn + c0]);

#pragma unroll
        for (int kk = 0; kk < 4; kk++) {
#pragma unroll
            for (int r = 0; r < 8; r++) {
                float xv = (kk == 0) ? xf[r].x : (kk == 1) ? xf[r].y
                         : (kk == 2) ? xf[r].z : xf[r].w;
                u64 xx = pk2(xv, xv);
                FMA2(acc[r][0], xx, w[kk].x, acc[r][0]);
                FMA2(acc[r][1], xx, w[kk].y, acc[r][1]);
            }
        }
    }

    ulonglong2 b = *reinterpret_cast<const ulonglong2*>(&bias[c0]);
#pragma unroll
    for (int r = 0; r < 8; r++) {
        ADD2(acc[r][0], acc[r][0], b.x);
        ADD2(acc[r][1], acc[r][1], b.y);
        ulonglong2 o; o.x = acc[r][0]; o.y = acc[r][1];
        *reinterpret_cast<ulonglong2*>(&dst[(r0 + r) * XS + c0]) = o;
    }
}

__global__ void __launch_bounds__(NTHREADS, 1)
attn_fused_kernel(const float* __restrict__ x,
                  const float* __restrict__ wq, const float* __restrict__ bq,
                  const float* __restrict__ wk, const float* __restrict__ bk,
                  const float* __restrict__ wv, const float* __restrict__ bv,
                  float* __restrict__ out)
{
    extern __shared__ float smem[];
    float* sX  = smem;                 // [64][260] raw input tile (kept for the gate)
    float* sQ  = sX  + Wn * XS;        // [64][260] Q
    float* sKV = sQ  + Wn * XS;        // [64][260] K, later overwritten with V
    float* sS  = sKV + Wn * XS;        // [64][68]  scores -> probabilities

    const int tid = threadIdx.x;
    const size_t bh = blockIdx.x;
    const float* xg = x   + bh * (size_t)(Wn * Cn);
    float*       og = out + bh * (size_t)(Wn * Cn);

    // ---- P0: stage X ----
    for (int i = tid; i < Wn * Cn / 4; i += NTHREADS) {
        int r = i >> 6;
        int c = (i & 63) << 2;
        float4 v = reinterpret_cast<const float4*>(xg)[i];
        *reinterpret_cast<float4*>(&sX[r * XS + c]) = v;
    }
    __syncthreads();

    const int wid  = tid >> 5;          // 0..15
    const int lane = tid & 31;
    const int r0 = (wid >> 1) << 3;     // row block: 8 rows
    const int c0 = ((wid & 1) << 7) + (lane << 2);  // col slab + lane cols

    // ---- P1: Q and K projections ----
    proj_gemm(sX, sQ,  wq, bq, r0, c0);
    proj_gemm(sX, sKV, wk, bk, r0, c0);
    __syncthreads();

    // ---- P2: S = K Q^T ; warp owns 4 q-rows, lane owns k-rows {lane, lane+32} ----
    {
        const int v0 = wid << 2;        // 4 q-rows per warp
        const int w0 = lane;
        u64 a0[4][2], a1[4][2];
#pragma unroll
        for (int j = 0; j < 4; j++) {
            a0[j][0] = a0[j][1] = 0ULL;
            a1[j][0] = a1[j][1] = 0ULL;
        }

#pragma unroll 2
        for (int c = 0; c < Cn; c += 4) {
            ulonglong2 k0 = *reinterpret_cast<const ulonglong2*>(&sKV[w0 * XS + c]);
            ulonglong2 k1 = *reinterpret_cast<const ulonglong2*>(&sKV[(w0 + 32) * XS + c]);
#pragma unroll
            for (int j = 0; j < 4; j++) {
                ulonglong2 q = *reinterpret_cast<const ulonglong2*>(&sQ[(v0 + j) * XS + c]); // broadcast
                FMA2(a0[j][0], k0.x, q.x, a0[j][0]);
                FMA2(a0[j][1], k0.y, q.y, a0[j][1]);
                FMA2(a1[j][0], k1.x, q.x, a1[j][0]);
                FMA2(a1[j][1], k1.y, q.y, a1[j][1]);
            }
        }

        float s0[4], s1[4];
#pragma unroll
        for (int j = 0; j < 4; j++) {
            float2 p00 = upk2(a0[j][0]), p01 = upk2(a0[j][1]);
            float2 p10 = upk2(a1[j][0]), p11 = upk2(a1[j][1]);
            s0[j] = (p00.x + p00.y) + (p01.x + p01.y);
            s1[j] = (p10.x + p10.y) + (p11.x + p11.y);
        }
        *reinterpret_cast<float4*>(&sS[w0 * SS + v0])        = make_float4(s0[0], s0[1], s0[2], s0[3]);
        *reinterpret_cast<float4*>(&sS[(w0 + 32) * SS + v0]) = make_float4(s1[0], s1[1], s1[2], s1[3]);
    }
    __syncthreads();

    // ---- P3: row softmax over v (warp handles rows wid*4 .. wid*4+3) ----
    {
#pragma unroll
        for (int rr = 0; rr < 4; rr++) {
            int r = (wid << 2) + rr;
            float aa = sS[r * SS + lane];
            float bb = sS[r * SS + lane + 32];
            float m = fmaxf(aa, bb);
#pragma unroll
            for (int off = 16; off > 0; off >>= 1)
                m = fmaxf(m, __shfl_xor_sync(0xffffffffu, m, off));
            float e0 = __expf(aa - m);
            float e1 = __expf(bb - m);
            float s = e0 + e1;
#pragma unroll
            for (int off = 16; off > 0; off >>= 1)
                s += __shfl_xor_sync(0xffffffffu, s, off);
            float inv = 1.0f / s;
            sS[r * SS + lane]      = e0 * inv;
            sS[r * SS + lane + 32] = e1 * inv;
        }
    }

    // ---- P4: V projection (overwrites K buffer; P2 reads done before last sync) ----
    proj_gemm(sX, sKV, wv, bv, r0, c0);
    __syncthreads();

    // ---- P5: O = P V (packed along channels), gate with X, store ----
    {
        u64 acc[8][2];
#pragma unroll
        for (int i = 0; i < 8; i++) { acc[i][0] = 0ULL; acc[i][1] = 0ULL; }

#pragma unroll 2
        for (int v = 0; v < Wn; v += 4) {
            float4 pf[8];
#pragma unroll
            for (int r = 0; r < 8; r++)
                pf[r] = *reinterpret_cast<const float4*>(&sS[(r0 + r) * SS + v]); // broadcast

            ulonglong2 va[4];
#pragma unroll
            for (int vv = 0; vv < 4; vv++)
                va[vv] = *reinterpret_cast<const ulonglong2*>(&sKV[(v + vv) * XS + c0]);

#pragma unroll
            for (int vv = 0; vv < 4; vv++) {
#pragma unroll
                for (int r = 0; r < 8; r++) {
                    float p = (vv == 0) ? pf[r].x : (vv == 1) ? pf[r].y
                            : (vv == 2) ? pf[r].z : pf[r].w;
                    u64 pp = pk2(p, p);
                    FMA2(acc[r][0], pp, va[vv].x, acc[r][0]);
                    FMA2(acc[r][1], pp, va[vv].y, acc[r][1]);
                }
            }
        }

#pragma unroll
        for (int r = 0; r < 8; r++) {
            float4 xr = *reinterpret_cast<const float4*>(&sX[(r0 + r) * XS + c0]);
            float2 a0 = upk2(acc[r][0]), a1 = upk2(acc[r][1]);
            float4 o = make_float4(a0.x * xr.x, a0.y * xr.y, a1.x * xr.z, a1.y * xr.w);
            *reinterpret_cast<float4*>(&og[(r0 + r) * Cn + c0]) = o;
        }
    }
}

extern "C" void kernel_launch(void* const* d_in, const int* in_sizes, int n_in,
                              void* d_out, int out_size)
{
    const float* x  = (const float*)d_in[0];
    const float* wq = (const float*)d_in[1];
    const float* bq = (const float*)d_in[2];
    const float* wk = (const float*)d_in[3];
    const float* bk = (const float*)d_in[4];
    const float* wv = (const float*)d_in[5];
    const float* bv = (const float*)d_in[6];
    float* out = (float*)d_out;

    int n_bh = in_sizes[0] / (Wn * Cn);   // B*H = 2048

    cudaFuncSetAttribute(attn_fused_kernel,
                         cudaFuncAttributeMaxDynamicSharedMemorySize, SMEM_BYTES);
    attn_fused_kernel<<<n_bh, NTHREADS, SMEM_BYTES>>>(x, wq, bq, wk, bk, wv, bv, out);
}